// round 1
// baseline (speedup 1.0000x reference)
#include <cuda_runtime.h>
#include <cuda_bf16.h>
#include <cstdint>

// Problem: x [64,512,1024] f32, W [1024,1024] f32 (torch Linear layout).
// y = x @ W^T  -> [B,S,F]; EMA over S: h_s = 0.5*h_{s-1} + 0.5*y_s.
// Output d_out = concat(hk [64,1024], hiddens [64,512,1024]) fp32.

#define BDIM 64
#define SDIM 512
#define FDIM 1024
#define MDIM (BDIM * SDIM)   // 32768
#define KDIM 1024

// ---------------- TF32 helpers ----------------
__device__ __forceinline__ unsigned f2tf32(float f) {
    unsigned r;
    asm("cvt.rna.tf32.f32 %0, %1;" : "=r"(r) : "f"(f));
    return r;
}

// ---------------- GEMM: C[M,N] = x[M,K] @ W[N,K]^T ----------------
// CTA tile 128x64x32, 256 threads, 8 warps in 4(M) x 2(N).
// Warp tile 32x32 = 2 (m16) x 4 (n8) mma tiles, k8 steps x4 per BK.
#define BM 128
#define BN 64
#define BK 32
#define SMEM_STRIDE 36   // +4 pad: bank = (4r + c) % 32, conflict-free frags

__global__ __launch_bounds__(256) void gemm_tf32_kernel(
    const float* __restrict__ x,
    const float* __restrict__ W,
    float* __restrict__ out)   // hiddens region, [M, FDIM]
{
    __shared__ unsigned As[BM][SMEM_STRIDE];
    __shared__ unsigned Bs[BN][SMEM_STRIDE];

    const int tid   = threadIdx.x;
    const int lane  = tid & 31;
    const int warp  = tid >> 5;
    const int warpM = warp & 3;   // 0..3
    const int warpN = warp >> 2;  // 0..1
    const int g     = lane >> 2;  // group id 0..7
    const int t     = lane & 3;   // thread-in-group 0..3

    const int blockN = blockIdx.x * BN;
    const int blockM = blockIdx.y * BM;

    float acc[2][4][4];
    #pragma unroll
    for (int i = 0; i < 2; i++)
        #pragma unroll
        for (int j = 0; j < 4; j++)
            #pragma unroll
            for (int k = 0; k < 4; k++)
                acc[i][j][k] = 0.0f;

    for (int k0 = 0; k0 < KDIM; k0 += BK) {
        // ---- load A tile: 128x32 floats = 1024 float4, 4 per thread ----
        #pragma unroll
        for (int i = 0; i < 4; i++) {
            int lin  = tid + i * 256;          // float4 index
            int row  = lin >> 3;               // 8 float4 per row
            int col4 = lin & 7;
            float4 v = *reinterpret_cast<const float4*>(
                x + (size_t)(blockM + row) * KDIM + k0 + col4 * 4);
            uint4 u;
            u.x = f2tf32(v.x); u.y = f2tf32(v.y);
            u.z = f2tf32(v.z); u.w = f2tf32(v.w);
            *reinterpret_cast<uint4*>(&As[row][col4 * 4]) = u;
        }
        // ---- load B tile: 64x32 floats = 512 float4, 2 per thread ----
        #pragma unroll
        for (int i = 0; i < 2; i++) {
            int lin  = tid + i * 256;
            int row  = lin >> 3;
            int col4 = lin & 7;
            float4 v = *reinterpret_cast<const float4*>(
                W + (size_t)(blockN + row) * KDIM + k0 + col4 * 4);
            uint4 u;
            u.x = f2tf32(v.x); u.y = f2tf32(v.y);
            u.z = f2tf32(v.z); u.w = f2tf32(v.w);
            *reinterpret_cast<uint4*>(&Bs[row][col4 * 4]) = u;
        }
        __syncthreads();

        #pragma unroll
        for (int kk = 0; kk < 4; kk++) {
            const int kb = kk * 8;
            unsigned a[2][4];
            #pragma unroll
            for (int mt = 0; mt < 2; mt++) {
                int arow = warpM * 32 + mt * 16 + g;
                a[mt][0] = As[arow    ][kb + t];
                a[mt][1] = As[arow + 8][kb + t];
                a[mt][2] = As[arow    ][kb + t + 4];
                a[mt][3] = As[arow + 8][kb + t + 4];
            }
            unsigned bf[4][2];
            #pragma unroll
            for (int nt = 0; nt < 4; nt++) {
                int bcol = warpN * 32 + nt * 8 + g;
                bf[nt][0] = Bs[bcol][kb + t];
                bf[nt][1] = Bs[bcol][kb + t + 4];
            }
            #pragma unroll
            for (int mt = 0; mt < 2; mt++) {
                #pragma unroll
                for (int nt = 0; nt < 4; nt++) {
                    asm volatile(
                        "mma.sync.aligned.m16n8k8.row.col.f32.tf32.tf32.f32 "
                        "{%0,%1,%2,%3}, {%4,%5,%6,%7}, {%8,%9}, {%0,%1,%2,%3};\n"
                        : "+f"(acc[mt][nt][0]), "+f"(acc[mt][nt][1]),
                          "+f"(acc[mt][nt][2]), "+f"(acc[mt][nt][3])
                        : "r"(a[mt][0]), "r"(a[mt][1]), "r"(a[mt][2]), "r"(a[mt][3]),
                          "r"(bf[nt][0]), "r"(bf[nt][1]));
                }
            }
        }
        __syncthreads();
    }

    // ---- epilogue: write y tile ----
    #pragma unroll
    for (int mt = 0; mt < 2; mt++) {
        #pragma unroll
        for (int nt = 0; nt < 4; nt++) {
            int row = blockM + warpM * 32 + mt * 16 + g;
            int col = blockN + warpN * 32 + nt * 8 + t * 2;
            out[(size_t)row * FDIM + col]            = acc[mt][nt][0];
            out[(size_t)row * FDIM + col + 1]        = acc[mt][nt][1];
            out[(size_t)(row + 8) * FDIM + col]      = acc[mt][nt][2];
            out[(size_t)(row + 8) * FDIM + col + 1]  = acc[mt][nt][3];
        }
    }
}

// ---------------- EMA scan over S, in place, writes hk ----------------
__global__ __launch_bounds__(256) void ema_scan_kernel(
    float* __restrict__ hid,   // [B, S, F] holding y, overwritten with h
    float* __restrict__ hk)    // [B, F]
{
    const int gid = blockIdx.x * blockDim.x + threadIdx.x;  // 0..65535
    const int b = gid >> 10;
    const int f = gid & 1023;
    float* p = hid + (size_t)b * SDIM * FDIM + f;

    float h = 0.0f;
    #pragma unroll 1
    for (int s = 0; s < SDIM; s += 8) {
        float v0 = p[(size_t)(s + 0) * FDIM];
        float v1 = p[(size_t)(s + 1) * FDIM];
        float v2 = p[(size_t)(s + 2) * FDIM];
        float v3 = p[(size_t)(s + 3) * FDIM];
        float v4 = p[(size_t)(s + 4) * FDIM];
        float v5 = p[(size_t)(s + 5) * FDIM];
        float v6 = p[(size_t)(s + 6) * FDIM];
        float v7 = p[(size_t)(s + 7) * FDIM];
        h = 0.5f * (h + v0); p[(size_t)(s + 0) * FDIM] = h;
        h = 0.5f * (h + v1); p[(size_t)(s + 1) * FDIM] = h;
        h = 0.5f * (h + v2); p[(size_t)(s + 2) * FDIM] = h;
        h = 0.5f * (h + v3); p[(size_t)(s + 3) * FDIM] = h;
        h = 0.5f * (h + v4); p[(size_t)(s + 4) * FDIM] = h;
        h = 0.5f * (h + v5); p[(size_t)(s + 5) * FDIM] = h;
        h = 0.5f * (h + v6); p[(size_t)(s + 6) * FDIM] = h;
        h = 0.5f * (h + v7); p[(size_t)(s + 7) * FDIM] = h;
    }
    hk[gid] = h;
}

extern "C" void kernel_launch(void* const* d_in, const int* in_sizes, int n_in,
                              void* d_out, int out_size) {
    const float* x = (const float*)d_in[0];   // [64, 512, 1024]
    const float* W = (const float*)d_in[1];   // [1024, 1024]
    float* out = (float*)d_out;
    float* hk  = out;                          // [64, 1024]
    float* hid = out + (size_t)BDIM * FDIM;    // [64, 512, 1024]

    dim3 grid(FDIM / BN, MDIM / BM);           // (16, 256)
    gemm_tf32_kernel<<<grid, 256>>>(x, W, hid);
    ema_scan_kernel<<<256, 256>>>(hid, hk);
}

// round 2
// speedup vs baseline: 1.3926x; 1.3926x over previous
#include <cuda_runtime.h>
#include <cuda_bf16.h>
#include <cstdint>

#define BDIM 64
#define SDIM 512
#define FDIM 1024
#define MDIM (BDIM * SDIM)   // 32768
#define KDIM 1024

// ---------------- device scratch: W pre-converted to tf32 (rna) ----------------
__device__ unsigned g_wtf32[FDIM * KDIM];   // 4 MB

__device__ __forceinline__ unsigned f2tf32(float f) {
    unsigned r;
    asm("cvt.rna.tf32.f32 %0, %1;" : "=r"(r) : "f"(f));
    return r;
}

__global__ __launch_bounds__(256) void convert_w_kernel(const float* __restrict__ W) {
    int i = blockIdx.x * blockDim.x + threadIdx.x;   // float4 index, 262144 total
    float4 v = *reinterpret_cast<const float4*>(W + (size_t)i * 4);
    uint4 u;
    u.x = f2tf32(v.x); u.y = f2tf32(v.y); u.z = f2tf32(v.z); u.w = f2tf32(v.w);
    *reinterpret_cast<uint4*>(g_wtf32 + (size_t)i * 4) = u;
}

// ---------------- cp.async helpers ----------------
__device__ __forceinline__ void cp_async16(void* smem, const void* gmem) {
    unsigned saddr = (unsigned)__cvta_generic_to_shared(smem);
    asm volatile("cp.async.cg.shared.global [%0], [%1], 16;\n" :: "r"(saddr), "l"(gmem));
}
__device__ __forceinline__ void cp_commit() {
    asm volatile("cp.async.commit_group;\n");
}
template <int N>
__device__ __forceinline__ void cp_wait() {
    asm volatile("cp.async.wait_group %0;\n" :: "n"(N));
}

// ---------------- pipelined TF32 GEMM: C[M,N] = x[M,K] @ W[N,K]^T ----------------
#define BM 128
#define BN 128
#define BK 32
#define STAGES 3
#define SMEM_STRIDE 36                      // +4 pad -> conflict-free scalar frag LDS
#define A_WORDS (BM * SMEM_STRIDE)          // 4608
#define B_WORDS (BN * SMEM_STRIDE)          // 4608
#define STAGE_WORDS (A_WORDS + B_WORDS)     // 9216
#define SMEM_BYTES (STAGES * STAGE_WORDS * 4)  // 110592

__global__ __launch_bounds__(256, 2) void gemm_tf32_pipe_kernel(
    const float* __restrict__ x,
    float* __restrict__ out)    // hiddens region [M, FDIM]
{
    extern __shared__ unsigned smem_buf[];

    const int tid   = threadIdx.x;
    const int lane  = tid & 31;
    const int warp  = tid >> 5;
    const int warpM = warp >> 2;   // 0..1  (64-row warp tile)
    const int warpN = warp & 3;    // 0..3  (32-col warp tile)
    const int g     = lane >> 2;   // 0..7
    const int t     = lane & 3;    // 0..3

    const int blockN = blockIdx.x * BN;
    const int blockM = blockIdx.y * BM;

    const unsigned* Wc = g_wtf32;

    float acc[4][4][4];
    #pragma unroll
    for (int i = 0; i < 4; i++)
        #pragma unroll
        for (int j = 0; j < 4; j++)
            #pragma unroll
            for (int k = 0; k < 4; k++)
                acc[i][j][k] = 0.0f;

    auto load_stage = [&](int stage, int k0) {
        unsigned* As = smem_buf + stage * STAGE_WORDS;
        unsigned* Bs = As + A_WORDS;
        #pragma unroll
        for (int i = 0; i < 4; i++) {
            int lin = tid + i * 256;        // 1024 float4 for A tile
            int row = lin >> 3;
            int c4  = lin & 7;
            cp_async16(&As[row * SMEM_STRIDE + c4 * 4],
                       x + (size_t)(blockM + row) * KDIM + k0 + c4 * 4);
        }
        #pragma unroll
        for (int i = 0; i < 4; i++) {
            int lin = lin = tid + i * 256;  // 1024 float4 for B tile
            int row = lin >> 3;
            int c4  = lin & 7;
            cp_async16(&Bs[row * SMEM_STRIDE + c4 * 4],
                       Wc + (size_t)(blockN + row) * KDIM + k0 + c4 * 4);
        }
    };

    // prologue: fill STAGES-1 stages
    #pragma unroll
    for (int s = 0; s < STAGES - 1; s++) {
        load_stage(s, s * BK);
        cp_commit();
    }

    const int KTILES = KDIM / BK;   // 32
    for (int kt = 0; kt < KTILES; kt++) {
        cp_wait<STAGES - 2>();
        __syncthreads();

        const unsigned* As = smem_buf + (kt % STAGES) * STAGE_WORDS;
        const unsigned* Bs = As + A_WORDS;

        #pragma unroll
        for (int kk = 0; kk < 4; kk++) {
            const int kb = kk * 8;
            unsigned a[4][4];
            #pragma unroll
            for (int mt = 0; mt < 4; mt++) {
                int ar = warpM * 64 + mt * 16 + g;
                a[mt][0] = As[ar * SMEM_STRIDE + kb + t];
                a[mt][1] = As[(ar + 8) * SMEM_STRIDE + kb + t];
                a[mt][2] = As[ar * SMEM_STRIDE + kb + t + 4];
                a[mt][3] = As[(ar + 8) * SMEM_STRIDE + kb + t + 4];
            }
            unsigned b[4][2];
            #pragma unroll
            for (int nt = 0; nt < 4; nt++) {
                int bc = warpN * 32 + nt * 8 + g;
                b[nt][0] = Bs[bc * SMEM_STRIDE + kb + t];
                b[nt][1] = Bs[bc * SMEM_STRIDE + kb + t + 4];
            }
            #pragma unroll
            for (int mt = 0; mt < 4; mt++) {
                #pragma unroll
                for (int nt = 0; nt < 4; nt++) {
                    asm volatile(
                        "mma.sync.aligned.m16n8k8.row.col.f32.tf32.tf32.f32 "
                        "{%0,%1,%2,%3}, {%4,%5,%6,%7}, {%8,%9}, {%0,%1,%2,%3};\n"
                        : "+f"(acc[mt][nt][0]), "+f"(acc[mt][nt][1]),
                          "+f"(acc[mt][nt][2]), "+f"(acc[mt][nt][3])
                        : "r"(a[mt][0]), "r"(a[mt][1]), "r"(a[mt][2]), "r"(a[mt][3]),
                          "r"(b[nt][0]), "r"(b[nt][1]));
                }
            }
        }

        int nk = kt + STAGES - 1;
        if (nk < KTILES) {
            load_stage(nk % STAGES, nk * BK);
        }
        cp_commit();
    }

    // epilogue: float2 stores
    #pragma unroll
    for (int mt = 0; mt < 4; mt++) {
        #pragma unroll
        for (int nt = 0; nt < 4; nt++) {
            int row = blockM + warpM * 64 + mt * 16 + g;
            int col = blockN + warpN * 32 + nt * 8 + t * 2;
            float2 v0 = make_float2(acc[mt][nt][0], acc[mt][nt][1]);
            float2 v1 = make_float2(acc[mt][nt][2], acc[mt][nt][3]);
            *reinterpret_cast<float2*>(out + (size_t)row * FDIM + col) = v0;
            *reinterpret_cast<float2*>(out + (size_t)(row + 8) * FDIM + col) = v1;
        }
    }
}

// ---------------- EMA scan over S, in place, writes hk ----------------
__global__ __launch_bounds__(256) void ema_scan_kernel(
    float* __restrict__ hid,   // [B, S, F] holding y, overwritten with h
    float* __restrict__ hk)    // [B, F]
{
    const int gid = blockIdx.x * blockDim.x + threadIdx.x;  // 0..65535
    const int b = gid >> 10;
    const int f = gid & 1023;
    float* p = hid + (size_t)b * SDIM * FDIM + f;

    float h = 0.0f;
    #pragma unroll 1
    for (int s = 0; s < SDIM; s += 16) {
        float v[16];
        #pragma unroll
        for (int i = 0; i < 16; i++)
            v[i] = __ldcs(p + (size_t)(s + i) * FDIM);
        #pragma unroll
        for (int i = 0; i < 16; i++) {
            h = 0.5f * (h + v[i]);
            __stcs(p + (size_t)(s + i) * FDIM, h);
        }
    }
    hk[gid] = h;
}

extern "C" void kernel_launch(void* const* d_in, const int* in_sizes, int n_in,
                              void* d_out, int out_size) {
    const float* x = (const float*)d_in[0];   // [64, 512, 1024]
    const float* W = (const float*)d_in[1];   // [1024, 1024]
    float* out = (float*)d_out;
    float* hk  = out;                          // [64, 1024]
    float* hid = out + (size_t)BDIM * FDIM;    // [64, 512, 1024]

    cudaFuncSetAttribute(gemm_tf32_pipe_kernel,
                         cudaFuncAttributeMaxDynamicSharedMemorySize, SMEM_BYTES);

    convert_w_kernel<<<1024, 256>>>(W);        // 1M float4 -> tf32
    dim3 grid(FDIM / BN, MDIM / BM);           // (8, 256)
    gemm_tf32_pipe_kernel<<<grid, 256, SMEM_BYTES>>>(x, hid);
    ema_scan_kernel<<<256, 256>>>(hid, hk);
}

// round 4
// speedup vs baseline: 2.1949x; 1.5761x over previous
#include <cuda_runtime.h>
#include <cuda_fp16.h>
#include <cstdint>

#define SDIM 512
#define FDIM 1024
#define KDIM 1024
#define MDIM 32768          // 64*512

// ---------------- device scratch (fp16 copies) ----------------
__device__ __half g_xh[(size_t)MDIM * KDIM];   // 64 MB
__device__ __half g_wh[(size_t)FDIM * KDIM];   // 2 MB

// ---------------- conversion kernels ----------------
__global__ __launch_bounds__(256) void convert_x_kernel(const float* __restrict__ x) {
    size_t i = ((size_t)blockIdx.x * 256 + threadIdx.x) * 8;
    float4 a = *reinterpret_cast<const float4*>(x + i);
    float4 b = *reinterpret_cast<const float4*>(x + i + 4);
    __half2 h0 = __floats2half2_rn(a.x, a.y);
    __half2 h1 = __floats2half2_rn(a.z, a.w);
    __half2 h2 = __floats2half2_rn(b.x, b.y);
    __half2 h3 = __floats2half2_rn(b.z, b.w);
    uint4 u;
    u.x = *reinterpret_cast<unsigned*>(&h0);
    u.y = *reinterpret_cast<unsigned*>(&h1);
    u.z = *reinterpret_cast<unsigned*>(&h2);
    u.w = *reinterpret_cast<unsigned*>(&h3);
    *reinterpret_cast<uint4*>(g_xh + i) = u;
}

__global__ __launch_bounds__(256) void convert_w_kernel(const float* __restrict__ W) {
    size_t i = ((size_t)blockIdx.x * 256 + threadIdx.x) * 8;
    float4 a = *reinterpret_cast<const float4*>(W + i);
    float4 b = *reinterpret_cast<const float4*>(W + i + 4);
    __half2 h0 = __floats2half2_rn(a.x, a.y);
    __half2 h1 = __floats2half2_rn(a.z, a.w);
    __half2 h2 = __floats2half2_rn(b.x, b.y);
    __half2 h3 = __floats2half2_rn(b.z, b.w);
    uint4 u;
    u.x = *reinterpret_cast<unsigned*>(&h0);
    u.y = *reinterpret_cast<unsigned*>(&h1);
    u.z = *reinterpret_cast<unsigned*>(&h2);
    u.w = *reinterpret_cast<unsigned*>(&h3);
    *reinterpret_cast<uint4*>(g_wh + i) = u;
}

// ---------------- PTX helpers ----------------
__device__ __forceinline__ void cp_async16(void* smem, const void* gmem) {
    unsigned saddr = (unsigned)__cvta_generic_to_shared(smem);
    asm volatile("cp.async.cg.shared.global [%0], [%1], 16;\n" :: "r"(saddr), "l"(gmem));
}
__device__ __forceinline__ void cp_commit() { asm volatile("cp.async.commit_group;\n"); }
__device__ __forceinline__ void cp_wait1() { asm volatile("cp.async.wait_group 1;\n"); }

#define LDSM_X4(r0, r1, r2, r3, addr) \
    asm volatile("ldmatrix.sync.aligned.m8n8.x4.shared.b16 {%0,%1,%2,%3}, [%4];" \
                 : "=r"(r0), "=r"(r1), "=r"(r2), "=r"(r3) : "r"(addr))

// ---------------- fp16 mma.sync GEMM: C[M,N] = xh[M,K] @ wh[N,K]^T ----------------
// CTA 128x128, BK=64 halves, 3 cp.async stages, 8 warps (2M x 4N), warp tile 64x32.
#define BM 128
#define BN 128
#define BK 64
#define ROW_B 144                       // 64 halves (128B) + 16B pad per row
#define TILE_B (128 * ROW_B)            // 18432 bytes (A or B tile)
#define STAGE_B (2 * TILE_B)            // 36864
#define STAGES 3
#define GEMM_SMEM (STAGES * STAGE_B)    // 110592

__global__ __launch_bounds__(256, 2) void gemm_fp16_kernel(float* __restrict__ out) {
    extern __shared__ char smem[];
    const uint32_t smem_base = (uint32_t)__cvta_generic_to_shared(smem);

    const int tid   = threadIdx.x;
    const int lane  = tid & 31;
    const int warp  = tid >> 5;
    const int warpM = warp >> 2;   // 0..1 (64 rows)
    const int warpN = warp & 3;    // 0..3 (32 cols)

    const int m0 = blockIdx.y * BM;
    const int n0 = blockIdx.x * BN;

    float acc[4][4][4];
    #pragma unroll
    for (int i = 0; i < 4; i++)
        #pragma unroll
        for (int j = 0; j < 4; j++)
            #pragma unroll
            for (int k = 0; k < 4; k++)
                acc[i][j][k] = 0.0f;

    auto load_stage = [&](int slot, int k0) {
        char* sa = smem + slot * STAGE_B;
        char* sb = sa + TILE_B;
        #pragma unroll
        for (int i = 0; i < 4; i++) {        // A: 1024 16B chunks
            int l = tid + i * 256;
            int row = l >> 3, c = l & 7;
            cp_async16(sa + row * ROW_B + c * 16,
                       g_xh + (size_t)(m0 + row) * KDIM + k0 + c * 8);
        }
        #pragma unroll
        for (int i = 0; i < 4; i++) {        // B: 1024 16B chunks
            int l = tid + i * 256;
            int row = l >> 3, c = l & 7;
            cp_async16(sb + row * ROW_B + c * 16,
                       g_wh + (size_t)(n0 + row) * KDIM + k0 + c * 8);
        }
    };

    load_stage(0, 0);  cp_commit();
    load_stage(1, BK); cp_commit();

    // per-thread ldmatrix address components (halves -> bytes)
    const int a_row = warpM * 64 + (lane & 15);          // + mt*16
    const int a_kc  = (lane >> 4) << 3;                  // 0 or 8 halves
    const int b_row = warpN * 32 + (lane & 7) + ((lane >> 4) << 3);  // + p*16
    const int b_kc  = ((lane >> 3) & 1) << 3;

    const int KTILES = KDIM / BK;   // 16
    for (int kt = 0; kt < KTILES; kt++) {
        cp_wait1();
        __syncthreads();

        // prefetch next stage (overlaps with compute below)
        if (kt + 2 < KTILES) load_stage((kt + 2) % STAGES, (kt + 2) * BK);
        cp_commit();

        const uint32_t sa = smem_base + (kt % STAGES) * STAGE_B;
        const uint32_t sb = sa + TILE_B;

        #pragma unroll
        for (int kk = 0; kk < 4; kk++) {
            const int kb = kk * 16;   // halves
            uint32_t a[4][4];
            #pragma unroll
            for (int mt = 0; mt < 4; mt++) {
                uint32_t addr = sa + (a_row + mt * 16) * ROW_B + (kb + a_kc) * 2;
                LDSM_X4(a[mt][0], a[mt][1], a[mt][2], a[mt][3], addr);
            }
            #pragma unroll
            for (int p = 0; p < 2; p++) {
                uint32_t b0, b1, b2, b3;
                uint32_t addr = sb + (b_row + p * 16) * ROW_B + (kb + b_kc) * 2;
                LDSM_X4(b0, b1, b2, b3, addr);
                #pragma unroll
                for (int mt = 0; mt < 4; mt++) {
                    asm volatile(
                        "mma.sync.aligned.m16n8k16.row.col.f32.f16.f16.f32 "
                        "{%0,%1,%2,%3}, {%4,%5,%6,%7}, {%8,%9}, {%0,%1,%2,%3};\n"
                        : "+f"(acc[mt][2*p][0]), "+f"(acc[mt][2*p][1]),
                          "+f"(acc[mt][2*p][2]), "+f"(acc[mt][2*p][3])
                        : "r"(a[mt][0]), "r"(a[mt][1]), "r"(a[mt][2]), "r"(a[mt][3]),
                          "r"(b0), "r"(b1));
                    asm volatile(
                        "mma.sync.aligned.m16n8k16.row.col.f32.f16.f16.f32 "
                        "{%0,%1,%2,%3}, {%4,%5,%6,%7}, {%8,%9}, {%0,%1,%2,%3};\n"
                        : "+f"(acc[mt][2*p+1][0]), "+f"(acc[mt][2*p+1][1]),
                          "+f"(acc[mt][2*p+1][2]), "+f"(acc[mt][2*p+1][3])
                        : "r"(a[mt][0]), "r"(a[mt][1]), "r"(a[mt][2]), "r"(a[mt][3]),
                          "r"(b2), "r"(b3));
                }
            }
        }
        __syncthreads();
    }

    // epilogue
    #pragma unroll
    for (int mt = 0; mt < 4; mt++) {
        #pragma unroll
        for (int nt = 0; nt < 4; nt++) {
            int row = m0 + warpM * 64 + mt * 16 + (lane >> 2);
            int col = n0 + warpN * 32 + nt * 8 + (lane & 3) * 2;
            *reinterpret_cast<float2*>(out + (size_t)row * FDIM + col) =
                make_float2(acc[mt][nt][0], acc[mt][nt][1]);
            *reinterpret_cast<float2*>(out + (size_t)(row + 8) * FDIM + col) =
                make_float2(acc[mt][nt][2], acc[mt][nt][3]);
        }
    }
}

// ---------------- chunked EMA scan ----------------
// 4 chunks of 128 along S; chunks>0 warm up with 32 prior steps (carry ~0.5^33).
__global__ __launch_bounds__(256) void ema_scan_kernel(
    float* __restrict__ hid, float* __restrict__ hk)
{
    const int gid = blockIdx.x * 256 + threadIdx.x;   // 262144
    const int f = gid & 1023;
    const int c = (gid >> 10) & 3;
    const int b = gid >> 12;
    float* p = hid + (size_t)b * SDIM * FDIM + f;
    const int s0 = c * 128;

    float h = 0.0f;
    if (c > 0) {
        #pragma unroll 1
        for (int s = s0 - 32; s < s0; s += 8) {
            float v[8];
            #pragma unroll
            for (int i = 0; i < 8; i++) v[i] = __ldcs(p + (size_t)(s + i) * FDIM);
            #pragma unroll
            for (int i = 0; i < 8; i++) h = 0.5f * (h + v[i]);
        }
    }
    #pragma unroll 1
    for (int s = s0; s < s0 + 128; s += 8) {
        float v[8];
        #pragma unroll
        for (int i = 0; i < 8; i++) v[i] = __ldcs(p + (size_t)(s + i) * FDIM);
        #pragma unroll
        for (int i = 0; i < 8; i++) {
            h = 0.5f * (h + v[i]);
            __stcs(p + (size_t)(s + i) * FDIM, h);
        }
    }
    if (c == 3) hk[b * FDIM + f] = h;
}

extern "C" void kernel_launch(void* const* d_in, const int* in_sizes, int n_in,
                              void* d_out, int out_size) {
    const float* x = (const float*)d_in[0];   // [64, 512, 1024]
    const float* W = (const float*)d_in[1];   // [1024, 1024]
    float* out = (float*)d_out;
    float* hk  = out;                          // [64, 1024]
    float* hid = out + (size_t)64 * FDIM;      // [64, 512, 1024]

    cudaFuncSetAttribute(gemm_fp16_kernel,
                         cudaFuncAttributeMaxDynamicSharedMemorySize, GEMM_SMEM);

    convert_x_kernel<<<16384, 256>>>(x);
    convert_w_kernel<<<512, 256>>>(W);
    dim3 grid(FDIM / BN, MDIM / BM);           // (8, 256)
    gemm_fp16_kernel<<<grid, 256, GEMM_SMEM>>>(hid);
    ema_scan_kernel<<<1024, 256>>>(hid, hk);
}